// round 5
// baseline (speedup 1.0000x reference)
#include <cuda_runtime.h>
#include <cuda_bf16.h>
#include <cstdint>

#define NROWS 8192
#define NDIM  128
#define NS    64

static constexpr float EXP_SCALE = 14.4269504088896340736f; // log2(e)/tau

// ---------------- device scratch ----------------
__device__ __align__(256) __nv_bfloat16 g_a [NROWS * NDIM];  // n1 * log2(e)/tau
__device__ __align__(256) __nv_bfloat16 g_b1[NROWS * NDIM];  // n1
__device__ __align__(256) __nv_bfloat16 g_b2[NROWS * NDIM];  // n2
__device__ float g_d12[NROWS];
__device__ float g_d11[NROWS];
__device__ float g_adv[NROWS];
__device__ float g_rowsum[2][NROWS];

// ---------------- helpers ----------------
__device__ __forceinline__ uint32_t smem_u32(const void* p) {
    uint32_t a;
    asm("{ .reg .u64 t; cvta.to.shared.u64 t, %1; cvt.u32.u64 %0, t; }" : "=r"(a) : "l"(p));
    return a;
}
__device__ __forceinline__ float warp_sum(float v) {
#pragma unroll
    for (int o = 16; o > 0; o >>= 1) v += __shfl_xor_sync(0xFFFFFFFFu, v, o);
    return v;
}
__device__ __forceinline__ float ex2f(float x) {
    float y; asm("ex2.approx.f32 %0, %1;" : "=f"(y) : "f"(x)); return y;
}
__device__ __forceinline__ void ldsm_x4(uint32_t& r0, uint32_t& r1, uint32_t& r2, uint32_t& r3,
                                        uint32_t addr) {
    asm volatile("ldmatrix.sync.aligned.m8n8.x4.shared.b16 {%0,%1,%2,%3}, [%4];"
                 : "=r"(r0), "=r"(r1), "=r"(r2), "=r"(r3) : "r"(addr));
}
__device__ __forceinline__ void mma_bf16(float& c0, float& c1, float& c2, float& c3,
                                         uint32_t a0, uint32_t a1, uint32_t a2, uint32_t a3,
                                         uint32_t b0, uint32_t b1) {
    asm volatile(
        "mma.sync.aligned.m16n8k16.row.col.f32.bf16.bf16.f32 "
        "{%0,%1,%2,%3},{%4,%5,%6,%7},{%8,%9},{%0,%1,%2,%3};"
        : "+f"(c0), "+f"(c1), "+f"(c2), "+f"(c3)
        : "r"(a0), "r"(a1), "r"(a2), "r"(a3), "r"(b0), "r"(b1));
}

// smem tile: 128 rows x 256B (128 bf16). chunk c (16B) swizzled: c' = c ^ (row & 7).
__device__ __forceinline__ uint32_t tile_addr(uint32_t base, uint32_t row, uint32_t chunk) {
    return base + row * 256u + ((chunk ^ (row & 7u)) << 4);
}

// load one [128 x 128] bf16 K-major tile into swizzled smem via cp.async (256 thr)
__device__ __forceinline__ void load_tile_async(uint32_t dst, const __nv_bfloat16* src) {
    const char* s = (const char*)src;
    int t = threadIdx.x;
#pragma unroll
    for (int j = 0; j < 8; ++j) {
        uint32_t q = (uint32_t)t + 256u * j;   // 2048 16B chunks
        uint32_t r = q >> 4, c = q & 15u;
        uint32_t d = tile_addr(dst, r, c);
        const char* g = s + ((size_t)r << 8) + ((size_t)c << 4);
        asm volatile("cp.async.cg.shared.global [%0], [%1], 16;" :: "r"(d), "l"(g) : "memory");
    }
    asm volatile("cp.async.commit_group;" ::: "memory");
}
#define CP_WAIT(n) asm volatile("cp.async.wait_group %0;" :: "n"(n) : "memory")

static constexpr int TILE_BYTES = 32768;
static constexpr int SMEM_A_OFF = 0;
static constexpr int SMEM_B_OFF = TILE_BYTES;
static constexpr int SMEM_DYN   = TILE_BYTES * 4;   // A + 3 B stages = 128KB

// ---------------- kernel A: normalize + diagonals + adversarial ----------------
__global__ void __launch_bounds__(256) prep_kernel(const float* __restrict__ z1,
                                                   const float* __restrict__ z2,
                                                   const float* __restrict__ cpre,
                                                   const float* __restrict__ lab) {
    int w = threadIdx.x >> 5, lane = threadIdx.x & 31;
    int row = blockIdx.x * 8 + w;
    float4 a = ((const float4*)(z1 + (size_t)row * NDIM))[lane];
    float4 b = ((const float4*)(z2 + (size_t)row * NDIM))[lane];
    float ss1 = warp_sum(a.x * a.x + a.y * a.y + a.z * a.z + a.w * a.w);
    float ss2 = warp_sum(b.x * b.x + b.y * b.y + b.z * b.z + b.w * b.w);
    float inv1 = 1.f / fmaxf(sqrtf(ss1), 1e-8f);
    float inv2 = 1.f / fmaxf(sqrtf(ss2), 1e-8f);
    float4 n1 = make_float4(a.x * inv1, a.y * inv1, a.z * inv1, a.w * inv1);
    float4 n2 = make_float4(b.x * inv2, b.y * inv2, b.z * inv2, b.w * inv2);
    float d12 = warp_sum(n1.x * n2.x + n1.y * n2.y + n1.z * n2.z + n1.w * n2.w);
    float d11 = warp_sum(n1.x * n1.x + n1.y * n1.y + n1.z * n1.z + n1.w * n1.w);

    __nv_bfloat162* pa = (__nv_bfloat162*)(g_a + (size_t)row * NDIM) + lane * 2;
    pa[0] = __floats2bfloat162_rn(n1.x * EXP_SCALE, n1.y * EXP_SCALE);
    pa[1] = __floats2bfloat162_rn(n1.z * EXP_SCALE, n1.w * EXP_SCALE);
    __nv_bfloat162* p1 = (__nv_bfloat162*)(g_b1 + (size_t)row * NDIM) + lane * 2;
    p1[0] = __floats2bfloat162_rn(n1.x, n1.y);
    p1[1] = __floats2bfloat162_rn(n1.z, n1.w);
    __nv_bfloat162* p2 = (__nv_bfloat162*)(g_b2 + (size_t)row * NDIM) + lane * 2;
    p2[0] = __floats2bfloat162_rn(n2.x, n2.y);
    p2[1] = __floats2bfloat162_rn(n2.z, n2.w);
    if (lane == 0) { g_d12[row] = d12; g_d11[row] = d11; }

    // adversarial: picked = c_norm[row, argmax(label_row)]  (first-max tie-break)
    float2 cc = ((const float2*)(cpre + (size_t)row * NS))[lane];
    float2 ll = ((const float2*)(lab + (size_t)row * NS))[lane];
    float csum = warp_sum(cc.x * cc.x + cc.y * cc.y);
    float bv = ll.x; int bi = lane * 2; float bc = cc.x;
    if (ll.y > bv) { bv = ll.y; bi = lane * 2 + 1; bc = cc.y; }
#pragma unroll
    for (int o = 16; o > 0; o >>= 1) {
        float ov = __shfl_xor_sync(0xFFFFFFFFu, bv, o);
        int   oi = __shfl_xor_sync(0xFFFFFFFFu, bi, o);
        float oc = __shfl_xor_sync(0xFFFFFFFFu, bc, o);
        if (ov > bv || (ov == bv && oi < bi)) { bv = ov; bi = oi; bc = oc; }
    }
    if (lane == 0) {
        float picked = bc / fmaxf(sqrtf(csum), 1e-12f);
        g_adv[row] = -logf(1e-12f + 1.f - picked);
    }
}

// ---------------- kernel B: fused sim-GEMM + exp row-sums (mma.sync bf16) ----------------
// grid (64, 2): x = 128-row A tile, y = matrix (0: vs n2 -> S12, 1: vs n1 -> S11)
// 8 warps: 4 M-slabs (32 rows) x 2 N-slabs (64 cols). A fragments persistent in regs.
__global__ void __launch_bounds__(256, 1) sim_rowsum_kernel() {
    extern __shared__ char smem_raw[];
    const uint32_t base = smem_u32(smem_raw);
    const int tid  = threadIdx.x;
    const int wid  = tid >> 5;
    const int lane = tid & 31;
    const int tile_i = blockIdx.x;
    const int mat    = blockIdx.y;
    const __nv_bfloat16* Asrc = g_a + (size_t)tile_i * 128 * NDIM;
    const __nv_bfloat16* Bsrc = mat ? g_b1 : g_b2;

    const int m_base = (wid & 3) * 32;   // warp M slab within CTA tile
    const int jslab  = wid >> 2;         // warp N slab (0/1), 64 cols each

    // prelude loads: A, B0, B1
    load_tile_async(base + SMEM_A_OFF, Asrc);
    load_tile_async(base + SMEM_B_OFF, Bsrc);
    load_tile_async(base + SMEM_B_OFF + TILE_BYTES, Bsrc + 128 * NDIM);

    CP_WAIT(2);          // A resident
    __syncthreads();

    // persistent A fragments: af[mblk][kblk][4]
    uint32_t af[2][8][4];
    {
        uint32_t r_a = (uint32_t)(m_base + (lane & 15));
        uint32_t g_hi = (uint32_t)(lane >> 4);          // 0/1 -> +8 elems
#pragma unroll
        for (int mb = 0; mb < 2; ++mb)
#pragma unroll
            for (int k = 0; k < 8; ++k) {
                uint32_t addr = tile_addr(base + SMEM_A_OFF, r_a + mb * 16u, 2u * k + g_hi);
                ldsm_x4(af[mb][k][0], af[mb][k][1], af[mb][k][2], af[mb][k][3], addr);
            }
    }

    // B ldmatrix per-lane row precompute: row = n_warp + nb*16 + (lane&7) + (lane>=16 ? 8 : 0)
    const uint32_t rB0 = (uint32_t)(jslab * 64 + (lane & 7) + ((lane >> 4) << 3));
    const uint32_t gB  = (uint32_t)((lane >> 3) & 1);   // k half

    float s00 = 0.f, s01 = 0.f, s10 = 0.f, s11 = 0.f;   // [mblk][rowhalf]

    for (int t = 0; t < 64; ++t) {
        if (t < 63) { CP_WAIT(1); } else { CP_WAIT(0); }
        __syncthreads();
        if (t + 2 < 64)
            load_tile_async(base + SMEM_B_OFF + (uint32_t)((t + 2) % 3) * TILE_BYTES,
                            Bsrc + (size_t)(t + 2) * 128 * NDIM);

        const uint32_t bstage = base + SMEM_B_OFF + (uint32_t)(t % 3) * TILE_BYTES;
        float c[2][8][4];
#pragma unroll
        for (int mb = 0; mb < 2; ++mb)
#pragma unroll
            for (int n = 0; n < 8; ++n)
#pragma unroll
                for (int q = 0; q < 4; ++q) c[mb][n][q] = 0.f;

#pragma unroll
        for (int k = 0; k < 8; ++k) {
            uint32_t bf[4][4];
#pragma unroll
            for (int nb = 0; nb < 4; ++nb) {
                uint32_t addr = tile_addr(bstage, rB0 + nb * 16u, 2u * k + gB);
                ldsm_x4(bf[nb][0], bf[nb][1], bf[nb][2], bf[nb][3], addr);
            }
#pragma unroll
            for (int mb = 0; mb < 2; ++mb)
#pragma unroll
                for (int nb = 0; nb < 4; ++nb) {
                    mma_bf16(c[mb][nb * 2][0], c[mb][nb * 2][1], c[mb][nb * 2][2], c[mb][nb * 2][3],
                             af[mb][k][0], af[mb][k][1], af[mb][k][2], af[mb][k][3],
                             bf[nb][0], bf[nb][1]);
                    mma_bf16(c[mb][nb * 2 + 1][0], c[mb][nb * 2 + 1][1],
                             c[mb][nb * 2 + 1][2], c[mb][nb * 2 + 1][3],
                             af[mb][k][0], af[mb][k][1], af[mb][k][2], af[mb][k][3],
                             bf[nb][2], bf[nb][3]);
                }
        }
        // epilogue: exp2 + row accumulation (c0,c1 -> row l/4 ; c2,c3 -> row l/4+8)
#pragma unroll
        for (int n = 0; n < 8; ++n) {
            s00 += ex2f(c[0][n][0]) + ex2f(c[0][n][1]);
            s01 += ex2f(c[0][n][2]) + ex2f(c[0][n][3]);
            s10 += ex2f(c[1][n][0]) + ex2f(c[1][n][1]);
            s11 += ex2f(c[1][n][2]) + ex2f(c[1][n][3]);
        }
    }

    // reduce across the 4 lanes sharing a row (lane%4 varies, same lane/4)
#pragma unroll
    for (int o = 1; o <= 2; o <<= 1) {
        s00 += __shfl_xor_sync(0xFFFFFFFFu, s00, o);
        s01 += __shfl_xor_sync(0xFFFFFFFFu, s01, o);
        s10 += __shfl_xor_sync(0xFFFFFFFFu, s10, o);
        s11 += __shfl_xor_sync(0xFFFFFFFFu, s11, o);
    }
    __syncthreads();                       // done reading smem tiles; reuse A region
    float* buf = (float*)smem_raw;         // buf[2][128]
    if ((lane & 3) == 0) {
        int r = m_base + (lane >> 2);
        buf[jslab * 128 + r]      = s00;
        buf[jslab * 128 + r + 8]  = s01;
        buf[jslab * 128 + r + 16] = s10;
        buf[jslab * 128 + r + 24] = s11;
    }
    __syncthreads();
    if (tid < 128)
        g_rowsum[mat][tile_i * 128 + tid] = buf[tid] + buf[tid + 128];
}

// ---------------- kernel C: final reduction ----------------
__global__ void __launch_bounds__(256) finish_kernel(float* __restrict__ out) {
    __shared__ float sc[256], sa[256];
    int tid = threadIdx.x;
    float c = 0.f, a = 0.f;
    for (int r = tid; r < NROWS; r += 256) {
        float num  = ex2f(EXP_SCALE * g_d12[r]);
        float diag = ex2f(EXP_SCALE * g_d11[r]);
        float den  = g_rowsum[0][r] + g_rowsum[1][r] - diag;
        c -= logf(1e-12f + num / den);
        a += g_adv[r];
    }
    sc[tid] = c; sa[tid] = a;
    __syncthreads();
    for (int s = 128; s > 0; s >>= 1) {
        if (tid < s) { sc[tid] += sc[tid + s]; sa[tid] += sa[tid + s]; }
        __syncthreads();
    }
    if (tid == 0)
        out[0] = sc[0] / (8192.0f * 16383.0f) + sa[0];
}

extern "C" void kernel_launch(void* const* d_in, const int* in_sizes, int n_in,
                              void* d_out, int out_size) {
    const float* z1  = (const float*)d_in[0];
    const float* z2  = (const float*)d_in[1];
    const float* c   = (const float*)d_in[2];
    const float* lab = (const float*)d_in[3];
    cudaFuncSetAttribute(sim_rowsum_kernel,
                         cudaFuncAttributeMaxDynamicSharedMemorySize, SMEM_DYN);
    prep_kernel<<<NROWS / 8, 256>>>(z1, z2, c, lab);
    dim3 g(64, 2);
    sim_rowsum_kernel<<<g, 256, SMEM_DYN>>>();
    finish_kernel<<<1, 256>>>((float*)d_out);
}